// round 16
// baseline (speedup 1.0000x reference)
#include <cuda_runtime.h>
#include <cuda_bf16.h>
#include <cstdint>

#define N_NODES_MAX 50000
#define E_MAX 1600000
#define DIM 128
#define NOUT 384
#define EPS_F 1e-6f

// ---------------- scratch (static device globals; no allocation) ----------------
__device__ __align__(16) __nv_bfloat16 g_Wall[NOUT * DIM];   // [Wchi; M1; M2]
__device__ __align__(16) float g_T[DIM * DIM];               // T = Wphi @ Wchi
__device__ __align__(16) __nv_bfloat16 g_Tab[(size_t)N_NODES_MAX * NOUT];  // per node: x|p|q (bf16)
__device__ int   g_count[N_NODES_MAX];
__device__ int   g_rowptr[N_NODES_MAX];
__device__ int   g_cursor[N_NODES_MAX];
__device__ int   g_total;
__device__ __align__(16) int4 g_epack[E_MAX];   // {col, bits(w), bits(ndot_c), 0} grouped by row
__device__ float g_normsq[N_NODES_MAX];
__device__ float g_ndot[N_NODES_MAX];

// ---------------- prep1: T = Wphi @ Wchi ; Wall rows 0-127 = bf16(Wchi)
__global__ void prep1_kernel(const float* __restrict__ Wchi,
                             const float* __restrict__ Wphi) {
    int i = blockIdx.x, j = threadIdx.x;
    float s = 0.f;
#pragma unroll 8
    for (int k = 0; k < DIM; k++) s += Wphi[i * DIM + k] * Wchi[k * DIM + j];
    g_T[i * DIM + j] = s;
    g_Wall[i * DIM + j] = __float2bfloat16(Wchi[i * DIM + j]);
}

// ---------------- prep2: M1 = T^T T ; M2 = Wv^T Wv   (both symmetric)
__global__ void prep2_kernel(const float* __restrict__ Wvphi) {
    int i = blockIdx.x, j = threadIdx.x;
    float s1 = 0.f, s2 = 0.f;
#pragma unroll 8
    for (int k = 0; k < DIM; k++) {
        s1 += g_T[k * DIM + i] * g_T[k * DIM + j];
        s2 += Wvphi[k * DIM + i] * Wvphi[k * DIM + j];
    }
    g_Wall[(128 + i) * DIM + j] = __float2bfloat16(s1);
    g_Wall[(256 + i) * DIM + j] = __float2bfloat16(s2);
}

// ---------------- x -> bf16 into table x-slot
__global__ void conv_x_kernel(const float* __restrict__ x, int nNodes) {
    int i = blockIdx.x * blockDim.x + threadIdx.x;
    if (i < nNodes * 64) {
        int node = i >> 6, kp = i & 63;
        float2 v = reinterpret_cast<const float2*>(x)[i];
        reinterpret_cast<__nv_bfloat162*>(g_Tab)[(size_t)node * 192 + kp] =
            __float22bfloat162_rn(v);
    }
}

// ---------------- hist: counts by row
__global__ void hist_kernel(const int* __restrict__ ei, int E) {
    int e = blockIdx.x * blockDim.x + threadIdx.x;
    if (e < E) atomicAdd(&g_count[ei[e]], 1);
}

// ---------------- alloc: CSR slot assignment (scan-by-atomic, block-aggregated)
__global__ void alloc_kernel(int nNodes) {
    int i = blockIdx.x * 256 + threadIdx.x;
    int lane = threadIdx.x & 31, warp = threadIdx.x >> 5;
    int c = (i < nNodes) ? g_count[i] : 0;
    int s = c;
#pragma unroll
    for (int o = 1; o < 32; o <<= 1) {
        int v = __shfl_up_sync(0xffffffffu, s, o);
        if (lane >= o) s += v;
    }
    __shared__ int wsum[8];
    __shared__ int blockBase;
    if (lane == 31) wsum[warp] = s;
    __syncthreads();
    if (threadIdx.x == 0) {
        int t = 0;
#pragma unroll
        for (int w = 0; w < 8; w++) { int v = wsum[w]; wsum[w] = t; t += v; }
        blockBase = atomicAdd(&g_total, t);
    }
    __syncthreads();
    int excl = blockBase + wsum[warp] + s - c;
    if (i < nNodes) { g_rowptr[i] = excl; g_cursor[i] = excl; }
}

// ---------------- bucket: scatter edges into CSR slots, baking in ndot[col]
__global__ void bucket_kernel(const int* __restrict__ ei,
                              const float* __restrict__ ew, int E) {
    int e = blockIdx.x * blockDim.x + threadIdx.x;
    if (e < E) {
        int r = ei[e];
        int c = ei[(size_t)E + e];
        int slot = atomicAdd(&g_cursor[r], 1);
        g_epack[slot] = make_int4(c, __float_as_int(ew[e]),
                                  __float_as_int(g_ndot[c]), 0);
    }
}

// ---------------- node GEMM, sliced: blockIdx.y = slice (0:normsq, 1:p, 2:q+ndot)
__global__ __launch_bounds__(256, 2) void gemm2_kernel(int nNodes) {
    extern __shared__ unsigned smem_u[];
    unsigned* Bs = smem_u;               // [128][68]
    unsigned* As = smem_u + 128 * 68;    // [128][68]
    float* sm_red = (float*)(smem_u + 2 * 128 * 68);  // [128]

    int tid = threadIdx.x;
    int slice = blockIdx.y;
    int base = blockIdx.x * 128;

    if (tid < 128) sm_red[tid] = 0.f;

    const unsigned* Wsrc = reinterpret_cast<const unsigned*>(g_Wall) + slice * 128 * 64;
    for (int idx = tid; idx < 128 * 64; idx += 256) {
        int n = idx >> 6, kp = idx & 63;
        Bs[n * 68 + kp] = Wsrc[idx];
    }
    const unsigned* Tsrc = reinterpret_cast<const unsigned*>(g_Tab);
    for (int idx = tid; idx < 128 * 64; idx += 256) {
        int r = idx >> 6, kp = idx & 63;
        int node = base + r;
        As[r * 68 + kp] = (node < nNodes) ? Tsrc[(size_t)node * 192 + kp] : 0u;
    }
    __syncthreads();

    int warp = tid >> 5, lane = tid & 31;
    int g = lane >> 2, tig = lane & 3;
    int wm = warp & 3, wn = warp >> 2;

    float acc[2][8][4];
#pragma unroll
    for (int t = 0; t < 2; t++)
#pragma unroll
        for (int nt = 0; nt < 8; nt++)
#pragma unroll
            for (int c = 0; c < 4; c++) acc[t][nt][c] = 0.f;

#pragma unroll
    for (int ks = 0; ks < 8; ks++) {
        unsigned a[2][4];
#pragma unroll
        for (int t = 0; t < 2; t++) {
            const unsigned* Ar = As + (wm * 32 + t * 16 + g) * 68 + ks * 8;
            a[t][0] = Ar[tig];
            a[t][1] = Ar[8 * 68 + tig];
            a[t][2] = Ar[tig + 4];
            a[t][3] = Ar[8 * 68 + tig + 4];
        }
#pragma unroll
        for (int nt = 0; nt < 8; nt++) {
            const unsigned* Br = Bs + (wn * 64 + nt * 8 + g) * 68 + ks * 8;
            unsigned b0 = Br[tig], b1 = Br[tig + 4];
#pragma unroll
            for (int t = 0; t < 2; t++) {
                asm volatile(
                    "mma.sync.aligned.m16n8k16.row.col.f32.bf16.bf16.f32 "
                    "{%0,%1,%2,%3},{%4,%5,%6,%7},{%8,%9},{%0,%1,%2,%3};\n"
                    : "+f"(acc[t][nt][0]), "+f"(acc[t][nt][1]),
                      "+f"(acc[t][nt][2]), "+f"(acc[t][nt][3])
                    : "r"(a[t][0]), "r"(a[t][1]), "r"(a[t][2]), "r"(a[t][3]),
                      "r"(b0), "r"(b1));
            }
        }
    }

    if (slice == 1 || slice == 2) {
        int colBase = (slice == 1) ? 128 : 256;
#pragma unroll
        for (int t = 0; t < 2; t++) {
            int ra = wm * 32 + t * 16 + g;
            int rb = ra + 8;
            int na = base + ra, nb = base + rb;
#pragma unroll
            for (int nt = 0; nt < 8; nt++) {
                int jc = wn * 64 + nt * 8 + 2 * tig;
                if (na < nNodes) {
                    __nv_bfloat162 h = __float22bfloat162_rn(
                        make_float2(acc[t][nt][0], acc[t][nt][1]));
                    *reinterpret_cast<unsigned*>(&g_Tab[(size_t)na * NOUT + colBase + jc]) =
                        *reinterpret_cast<unsigned*>(&h);
                }
                if (nb < nNodes) {
                    __nv_bfloat162 h = __float22bfloat162_rn(
                        make_float2(acc[t][nt][2], acc[t][nt][3]));
                    *reinterpret_cast<unsigned*>(&g_Tab[(size_t)nb * NOUT + colBase + jc]) =
                        *reinterpret_cast<unsigned*>(&h);
                }
            }
        }
    }

    if (slice == 0) {
#pragma unroll
        for (int t = 0; t < 2; t++) {
            int ra = wm * 32 + t * 16 + g, rb = ra + 8;
            float sa = 0.f, sb = 0.f;
#pragma unroll
            for (int nt = 0; nt < 8; nt++) {
                sa += acc[t][nt][0] * acc[t][nt][0] + acc[t][nt][1] * acc[t][nt][1];
                sb += acc[t][nt][2] * acc[t][nt][2] + acc[t][nt][3] * acc[t][nt][3];
            }
            atomicAdd(&sm_red[ra], sa);
            atomicAdd(&sm_red[rb], sb);
        }
        __syncthreads();
        if (tid < 128 && base + tid < nNodes) g_normsq[base + tid] = sm_red[tid];
    } else if (slice == 2) {
#pragma unroll
        for (int t = 0; t < 2; t++) {
            int ra = wm * 32 + t * 16 + g, rb = ra + 8;
            float sa = 0.f, sb = 0.f;
#pragma unroll
            for (int nt = 0; nt < 8; nt++) {
                int jp = (wn * 64 + nt * 8 + 2 * tig) >> 1;
                unsigned xa = As[ra * 68 + jp];
                unsigned xb = As[rb * 68 + jp];
                float2 fa = __bfloat1622float2(*reinterpret_cast<__nv_bfloat162*>(&xa));
                float2 fb = __bfloat1622float2(*reinterpret_cast<__nv_bfloat162*>(&xb));
                sa += fa.x * acc[t][nt][0] + fa.y * acc[t][nt][1];
                sb += fb.x * acc[t][nt][2] + fb.y * acc[t][nt][3];
            }
            atomicAdd(&sm_red[ra], sa);
            atomicAdd(&sm_red[rb], sb);
        }
        __syncthreads();
        if (tid < 128 && base + tid < nNodes) g_ndot[base + tid] = sm_red[tid];
    }
}

// ---------------- row kernel: warp per row, half-warp per edge, depth-2 pipeline
// Symmetry: dotz = p_r . x_c ; dq = q_r . x_c ; ndot_c baked in epack
__device__ __forceinline__ void unpack8(uint4 u, float* f) {
    float2 t;
    t = __bfloat1622float2(*reinterpret_cast<__nv_bfloat162*>(&u.x)); f[0] = t.x; f[1] = t.y;
    t = __bfloat1622float2(*reinterpret_cast<__nv_bfloat162*>(&u.y)); f[2] = t.x; f[3] = t.y;
    t = __bfloat1622float2(*reinterpret_cast<__nv_bfloat162*>(&u.z)); f[4] = t.x; f[5] = t.y;
    t = __bfloat1622float2(*reinterpret_cast<__nv_bfloat162*>(&u.w)); f[6] = t.x; f[7] = t.y;
}
// tanh(a)*tanh(b), a,b >= 0
__device__ __forceinline__ float tanh2_prod(float a, float b) {
    float e1 = __expf(-2.0f * a);
    float e2 = __expf(-2.0f * b);
    float num = (1.0f - e1) * (1.0f - e2);
    float den = (1.0f + e1) * (1.0f + e2);
    return num * __frcp_rn(den);
}
__device__ __forceinline__ float tanh_pos(float x) {
    float e = __expf(-2.0f * x);
    return (1.0f - e) * __frcp_rn(1.0f + e);
}

__global__ __launch_bounds__(256) void row_kernel(const float* __restrict__ x,
                                                  float* __restrict__ out, int nNodes) {
    int r = (int)((blockIdx.x * 256u + threadIdx.x) >> 5);
    int lane = threadIdx.x & 31;
    if (r >= nNodes) return;
    int hw = lane >> 4;
    int l16 = lane & 15;
    unsigned hmask = hw ? 0xFFFF0000u : 0x0000FFFFu;

    const uint4* tr = reinterpret_cast<const uint4*>(g_Tab + (size_t)r * NOUT);
    float xr[8], pr[8], qr[8];
    unpack8(tr[l16], xr);
    unpack8(tr[16 + l16], pr);
    unpack8(tr[32 + l16], qr);
    float nr = g_ndot[r];

    float acc[8];
#pragma unroll
    for (int k = 0; k < 8; k++) acc[k] = 0.f;
    float wsum = 0.f;

    int start = g_rowptr[r];
    int cnt = g_count[r];

    int i0 = hw;
    if (i0 < cnt) {
        // prologue: stages 0 and 1 in flight
        int4 pk0 = __ldg(&g_epack[start + i0]);
        uint4 x0 = reinterpret_cast<const uint4*>(g_Tab + (size_t)pk0.x * NOUT)[l16];
        int i1 = i0 + 2;
        int p1 = (i1 < cnt) ? i1 : i0;
        int4 pk1 = __ldg(&g_epack[start + p1]);
        uint4 x1 = reinterpret_cast<const uint4*>(g_Tab + (size_t)pk1.x * NOUT)[l16];

        while (i0 < cnt) {
            // issue stage-2 prefetch (clamped; dup never processed)
            int i2 = i0 + 4;
            int p2 = (i2 < cnt) ? i2 : i0;
            int4 pk2 = __ldg(&g_epack[start + p2]);
            uint4 x2 = reinterpret_cast<const uint4*>(g_Tab + (size_t)pk2.x * NOUT)[l16];

            // process stage 0
            float w = __int_as_float(pk0.y);
            float ncv = __int_as_float(pk0.z);

            float xc[8];
            unpack8(x0, xc);

            float dotz = 0.f, dq = 0.f;
#pragma unroll
            for (int k = 0; k < 8; k++) {
                dotz += pr[k] * xc[k];
                dq   += qr[k] * xc[k];
            }
#pragma unroll
            for (int o = 8; o; o >>= 1) {
                dotz += __shfl_xor_sync(hmask, dotz, o);
                dq   += __shfl_xor_sync(hmask, dq, o);
            }

            float nv = fmaxf(nr + ncv - 2.0f * dq, 0.0f);
            float s = w * tanh2_prod(fabsf(dotz), rsqrtf(nv));
            wsum += w;

#pragma unroll
            for (int k = 0; k < 8; k++) acc[k] += s * (xr[k] - xc[k]);

            // rotate stages
            i0 += 2;
            pk0 = pk1; x0 = x1;
            pk1 = pk2; x1 = x2;
        }
    }

#pragma unroll
    for (int k = 0; k < 8; k++)
        acc[k] += __shfl_xor_sync(0xffffffffu, acc[k], 16);
    wsum += __shfl_xor_sync(0xffffffffu, wsum, 16);

    float coef = (cnt > 0) ? __fdividef(1.0f, wsum * tanh_pos(sqrtf(g_normsq[r]))) : 0.f;

    int unit = 2 * l16 + hw;
    int sel = 4 * hw;
    const float4 xv = reinterpret_cast<const float4*>(x + (size_t)r * DIM)[unit];
    reinterpret_cast<float4*>(out + (size_t)r * DIM)[unit] =
        make_float4(xv.x - coef * acc[sel + 0], xv.y - coef * acc[sel + 1],
                    xv.z - coef * acc[sel + 2], xv.w - coef * acc[sel + 3]);
}

// ---------------- launch ----------------
// Order keeps gemm2 as the 6th launch (ncu -s 5 -c 1 captures it)
extern "C" void kernel_launch(void* const* d_in, const int* in_sizes, int n_in,
                              void* d_out, int out_size) {
    const float* x     = (const float*)d_in[0];
    const int*   ei    = (const int*)d_in[1];   // JAX emits int32
    const float* ew    = (const float*)d_in[2];
    const float* Wchi  = (const float*)d_in[3];
    const float* Wphi  = (const float*)d_in[4];
    const float* Wvphi = (const float*)d_in[5];

    int nNodes = in_sizes[0] / DIM;
    if (nNodes > N_NODES_MAX) nNodes = N_NODES_MAX;
    int E = in_sizes[2];
    if (E > E_MAX) E = E_MAX;

    void *pCnt, *pTot;
    cudaGetSymbolAddress(&pCnt, g_count);
    cudaGetSymbolAddress(&pTot, g_total);
    cudaMemsetAsync(pCnt, 0, (size_t)nNodes * sizeof(int), 0);
    cudaMemsetAsync(pTot, 0, sizeof(int), 0);

    prep1_kernel<<<DIM, DIM>>>(Wchi, Wphi);
    prep2_kernel<<<DIM, DIM>>>(Wvphi);

    int nUnits = nNodes * 64;
    conv_x_kernel<<<(nUnits + 255) / 256, 256>>>(x, nNodes);

    int smem = (2 * 128 * 68 + 128) * 4;
    cudaFuncSetAttribute(gemm2_kernel, cudaFuncAttributeMaxDynamicSharedMemorySize, smem);
    dim3 ggrid((nNodes + 127) / 128, 3);
    gemm2_kernel<<<ggrid, 256, smem>>>(nNodes);

    hist_kernel<<<(E + 255) / 256, 256>>>(ei, E);
    alloc_kernel<<<(nNodes + 255) / 256, 256>>>(nNodes);
    bucket_kernel<<<(E + 255) / 256, 256>>>(ei, ew, E);

    row_kernel<<<(nNodes * 32 + 255) / 256, 256>>>(x, (float*)d_out, nNodes);
}

// round 17
// speedup vs baseline: 1.2353x; 1.2353x over previous
#include <cuda_runtime.h>
#include <cuda_bf16.h>
#include <cstdint>

#define N_NODES_MAX 50000
#define E_MAX 1600000
#define DIM 128
#define NOUT 384
#define EPS_F 1e-6f

// ---------------- scratch (static device globals; no allocation) ----------------
__device__ __align__(16) __nv_bfloat16 g_Wall[NOUT * DIM];   // [Wchi; M1; M2]
__device__ __align__(16) float g_T[DIM * DIM];               // T = Wphi @ Wchi
__device__ __align__(16) __nv_bfloat16 g_Tab[(size_t)N_NODES_MAX * NOUT];  // per node: x|p|q (bf16)
__device__ int   g_count[N_NODES_MAX];
__device__ int   g_rowptr[N_NODES_MAX];
__device__ int   g_cursor[N_NODES_MAX];
__device__ int   g_total;
__device__ __align__(16) int4 g_epack[E_MAX];   // {col, bits(w), bits(ndot_c), 0} grouped by row
__device__ float g_normsq[N_NODES_MAX];
__device__ float g_ndot[N_NODES_MAX];

// ---------------- prep1: T = Wphi @ Wchi ; Wall rows 0-127 = bf16(Wchi)
__global__ void prep1_kernel(const float* __restrict__ Wchi,
                             const float* __restrict__ Wphi) {
    int i = blockIdx.x, j = threadIdx.x;
    float s = 0.f;
#pragma unroll 8
    for (int k = 0; k < DIM; k++) s += Wphi[i * DIM + k] * Wchi[k * DIM + j];
    g_T[i * DIM + j] = s;
    g_Wall[i * DIM + j] = __float2bfloat16(Wchi[i * DIM + j]);
}

// ---------------- prep2: M1 = T^T T ; M2 = Wv^T Wv   (both symmetric)
__global__ void prep2_kernel(const float* __restrict__ Wvphi) {
    int i = blockIdx.x, j = threadIdx.x;
    float s1 = 0.f, s2 = 0.f;
#pragma unroll 8
    for (int k = 0; k < DIM; k++) {
        s1 += g_T[k * DIM + i] * g_T[k * DIM + j];
        s2 += Wvphi[k * DIM + i] * Wvphi[k * DIM + j];
    }
    g_Wall[(128 + i) * DIM + j] = __float2bfloat16(s1);
    g_Wall[(256 + i) * DIM + j] = __float2bfloat16(s2);
}

// ---------------- x -> bf16 into table x-slot
__global__ void conv_x_kernel(const float* __restrict__ x, int nNodes) {
    int i = blockIdx.x * blockDim.x + threadIdx.x;
    if (i < nNodes * 64) {
        int node = i >> 6, kp = i & 63;
        float2 v = reinterpret_cast<const float2*>(x)[i];
        reinterpret_cast<__nv_bfloat162*>(g_Tab)[(size_t)node * 192 + kp] =
            __float22bfloat162_rn(v);
    }
}

// ---------------- hist: counts by row
__global__ void hist_kernel(const int* __restrict__ ei, int E) {
    int e = blockIdx.x * blockDim.x + threadIdx.x;
    if (e < E) atomicAdd(&g_count[ei[e]], 1);
}

// ---------------- alloc: CSR slot assignment (scan-by-atomic, block-aggregated)
__global__ void alloc_kernel(int nNodes) {
    int i = blockIdx.x * 256 + threadIdx.x;
    int lane = threadIdx.x & 31, warp = threadIdx.x >> 5;
    int c = (i < nNodes) ? g_count[i] : 0;
    int s = c;
#pragma unroll
    for (int o = 1; o < 32; o <<= 1) {
        int v = __shfl_up_sync(0xffffffffu, s, o);
        if (lane >= o) s += v;
    }
    __shared__ int wsum[8];
    __shared__ int blockBase;
    if (lane == 31) wsum[warp] = s;
    __syncthreads();
    if (threadIdx.x == 0) {
        int t = 0;
#pragma unroll
        for (int w = 0; w < 8; w++) { int v = wsum[w]; wsum[w] = t; t += v; }
        blockBase = atomicAdd(&g_total, t);
    }
    __syncthreads();
    int excl = blockBase + wsum[warp] + s - c;
    if (i < nNodes) { g_rowptr[i] = excl; g_cursor[i] = excl; }
}

// ---------------- bucket: scatter edges into CSR slots, baking in ndot[col]
__global__ void bucket_kernel(const int* __restrict__ ei,
                              const float* __restrict__ ew, int E) {
    int e = blockIdx.x * blockDim.x + threadIdx.x;
    if (e < E) {
        int r = ei[e];
        int c = ei[(size_t)E + e];
        int slot = atomicAdd(&g_cursor[r], 1);
        g_epack[slot] = make_int4(c, __float_as_int(ew[e]),
                                  __float_as_int(g_ndot[c]), 0);
    }
}

// ---------------- node GEMM, sliced: blockIdx.y = slice (0:normsq, 1:p, 2:q+ndot)
__global__ __launch_bounds__(256, 2) void gemm2_kernel(int nNodes) {
    extern __shared__ unsigned smem_u[];
    unsigned* Bs = smem_u;               // [128][68]
    unsigned* As = smem_u + 128 * 68;    // [128][68]
    float* sm_red = (float*)(smem_u + 2 * 128 * 68);  // [128]

    int tid = threadIdx.x;
    int slice = blockIdx.y;
    int base = blockIdx.x * 128;

    if (tid < 128) sm_red[tid] = 0.f;

    const unsigned* Wsrc = reinterpret_cast<const unsigned*>(g_Wall) + slice * 128 * 64;
    for (int idx = tid; idx < 128 * 64; idx += 256) {
        int n = idx >> 6, kp = idx & 63;
        Bs[n * 68 + kp] = Wsrc[idx];
    }
    const unsigned* Tsrc = reinterpret_cast<const unsigned*>(g_Tab);
    for (int idx = tid; idx < 128 * 64; idx += 256) {
        int r = idx >> 6, kp = idx & 63;
        int node = base + r;
        As[r * 68 + kp] = (node < nNodes) ? Tsrc[(size_t)node * 192 + kp] : 0u;
    }
    __syncthreads();

    int warp = tid >> 5, lane = tid & 31;
    int g = lane >> 2, tig = lane & 3;
    int wm = warp & 3, wn = warp >> 2;

    float acc[2][8][4];
#pragma unroll
    for (int t = 0; t < 2; t++)
#pragma unroll
        for (int nt = 0; nt < 8; nt++)
#pragma unroll
            for (int c = 0; c < 4; c++) acc[t][nt][c] = 0.f;

#pragma unroll
    for (int ks = 0; ks < 8; ks++) {
        unsigned a[2][4];
#pragma unroll
        for (int t = 0; t < 2; t++) {
            const unsigned* Ar = As + (wm * 32 + t * 16 + g) * 68 + ks * 8;
            a[t][0] = Ar[tig];
            a[t][1] = Ar[8 * 68 + tig];
            a[t][2] = Ar[tig + 4];
            a[t][3] = Ar[8 * 68 + tig + 4];
        }
#pragma unroll
        for (int nt = 0; nt < 8; nt++) {
            const unsigned* Br = Bs + (wn * 64 + nt * 8 + g) * 68 + ks * 8;
            unsigned b0 = Br[tig], b1 = Br[tig + 4];
#pragma unroll
            for (int t = 0; t < 2; t++) {
                asm volatile(
                    "mma.sync.aligned.m16n8k16.row.col.f32.bf16.bf16.f32 "
                    "{%0,%1,%2,%3},{%4,%5,%6,%7},{%8,%9},{%0,%1,%2,%3};\n"
                    : "+f"(acc[t][nt][0]), "+f"(acc[t][nt][1]),
                      "+f"(acc[t][nt][2]), "+f"(acc[t][nt][3])
                    : "r"(a[t][0]), "r"(a[t][1]), "r"(a[t][2]), "r"(a[t][3]),
                      "r"(b0), "r"(b1));
            }
        }
    }

    if (slice == 1 || slice == 2) {
        int colBase = (slice == 1) ? 128 : 256;
#pragma unroll
        for (int t = 0; t < 2; t++) {
            int ra = wm * 32 + t * 16 + g;
            int rb = ra + 8;
            int na = base + ra, nb = base + rb;
#pragma unroll
            for (int nt = 0; nt < 8; nt++) {
                int jc = wn * 64 + nt * 8 + 2 * tig;
                if (na < nNodes) {
                    __nv_bfloat162 h = __float22bfloat162_rn(
                        make_float2(acc[t][nt][0], acc[t][nt][1]));
                    *reinterpret_cast<unsigned*>(&g_Tab[(size_t)na * NOUT + colBase + jc]) =
                        *reinterpret_cast<unsigned*>(&h);
                }
                if (nb < nNodes) {
                    __nv_bfloat162 h = __float22bfloat162_rn(
                        make_float2(acc[t][nt][2], acc[t][nt][3]));
                    *reinterpret_cast<unsigned*>(&g_Tab[(size_t)nb * NOUT + colBase + jc]) =
                        *reinterpret_cast<unsigned*>(&h);
                }
            }
        }
    }

    if (slice == 0) {
#pragma unroll
        for (int t = 0; t < 2; t++) {
            int ra = wm * 32 + t * 16 + g, rb = ra + 8;
            float sa = 0.f, sb = 0.f;
#pragma unroll
            for (int nt = 0; nt < 8; nt++) {
                sa += acc[t][nt][0] * acc[t][nt][0] + acc[t][nt][1] * acc[t][nt][1];
                sb += acc[t][nt][2] * acc[t][nt][2] + acc[t][nt][3] * acc[t][nt][3];
            }
            atomicAdd(&sm_red[ra], sa);
            atomicAdd(&sm_red[rb], sb);
        }
        __syncthreads();
        if (tid < 128 && base + tid < nNodes) g_normsq[base + tid] = sm_red[tid];
    } else if (slice == 2) {
#pragma unroll
        for (int t = 0; t < 2; t++) {
            int ra = wm * 32 + t * 16 + g, rb = ra + 8;
            float sa = 0.f, sb = 0.f;
#pragma unroll
            for (int nt = 0; nt < 8; nt++) {
                int jp = (wn * 64 + nt * 8 + 2 * tig) >> 1;
                unsigned xa = As[ra * 68 + jp];
                unsigned xb = As[rb * 68 + jp];
                float2 fa = __bfloat1622float2(*reinterpret_cast<__nv_bfloat162*>(&xa));
                float2 fb = __bfloat1622float2(*reinterpret_cast<__nv_bfloat162*>(&xb));
                sa += fa.x * acc[t][nt][0] + fa.y * acc[t][nt][1];
                sb += fb.x * acc[t][nt][2] + fb.y * acc[t][nt][3];
            }
            atomicAdd(&sm_red[ra], sa);
            atomicAdd(&sm_red[rb], sb);
        }
        __syncthreads();
        if (tid < 128 && base + tid < nNodes) g_ndot[base + tid] = sm_red[tid];
    }
}

// ---------------- row kernel: warp per row, half-warp per edge, depth-1 pipeline
// Symmetry: dotz = p_r . x_c ; dq = q_r . x_c ; ndot_c baked in epack
// Algebra: sum_e s*(xr - xc) = ssum*xr - sum_e s*xc  (saves 8 FSUB per edge)
__device__ __forceinline__ void unpack8(uint4 u, float* f) {
    float2 t;
    t = __bfloat1622float2(*reinterpret_cast<__nv_bfloat162*>(&u.x)); f[0] = t.x; f[1] = t.y;
    t = __bfloat1622float2(*reinterpret_cast<__nv_bfloat162*>(&u.y)); f[2] = t.x; f[3] = t.y;
    t = __bfloat1622float2(*reinterpret_cast<__nv_bfloat162*>(&u.z)); f[4] = t.x; f[5] = t.y;
    t = __bfloat1622float2(*reinterpret_cast<__nv_bfloat162*>(&u.w)); f[6] = t.x; f[7] = t.y;
}
// tanh(a)*tanh(b), a,b >= 0
__device__ __forceinline__ float tanh2_prod(float a, float b) {
    float e1 = __expf(-2.0f * a);
    float e2 = __expf(-2.0f * b);
    float num = (1.0f - e1) * (1.0f - e2);
    float den = (1.0f + e1) * (1.0f + e2);
    return num * __frcp_rn(den);
}
__device__ __forceinline__ float tanh_pos(float x) {
    float e = __expf(-2.0f * x);
    return (1.0f - e) * __frcp_rn(1.0f + e);
}

__global__ __launch_bounds__(256) void row_kernel(const float* __restrict__ x,
                                                  float* __restrict__ out, int nNodes) {
    int r = (int)((blockIdx.x * 256u + threadIdx.x) >> 5);
    int lane = threadIdx.x & 31;
    if (r >= nNodes) return;
    int hw = lane >> 4;
    int l16 = lane & 15;
    unsigned hmask = hw ? 0xFFFF0000u : 0x0000FFFFu;

    const uint4* tr = reinterpret_cast<const uint4*>(g_Tab + (size_t)r * NOUT);
    float xr[8], pr[8], qr[8];
    unpack8(tr[l16], xr);
    unpack8(tr[16 + l16], pr);
    unpack8(tr[32 + l16], qr);
    float nr = g_ndot[r];

    float sacc[8];
#pragma unroll
    for (int k = 0; k < 8; k++) sacc[k] = 0.f;
    float wsum = 0.f, ssum = 0.f;

    int start = g_rowptr[r];
    int cnt = g_count[r];

    int idx = hw;
    if (idx < cnt) {
        int4 pk = __ldg(&g_epack[start + idx]);
        uint4 xcu = reinterpret_cast<const uint4*>(g_Tab + (size_t)pk.x * NOUT)[l16];

        while (true) {
            int idn = idx + 2;
            bool more = idn < cnt;
            int pidx = more ? idn : idx;
            int4 pkn = __ldg(&g_epack[start + pidx]);
            uint4 xcn = reinterpret_cast<const uint4*>(g_Tab + (size_t)pkn.x * NOUT)[l16];

            float w = __int_as_float(pk.y);
            float ncv = __int_as_float(pk.z);

            float xc[8];
            unpack8(xcu, xc);

            float dotz = 0.f, dq = 0.f;
#pragma unroll
            for (int k = 0; k < 8; k++) {
                dotz += pr[k] * xc[k];
                dq   += qr[k] * xc[k];
            }
#pragma unroll
            for (int o = 8; o; o >>= 1) {
                dotz += __shfl_xor_sync(hmask, dotz, o);
                dq   += __shfl_xor_sync(hmask, dq, o);
            }

            float nv = fmaxf(nr + ncv - 2.0f * dq, 0.0f);
            float s = w * tanh2_prod(fabsf(dotz), rsqrtf(nv));
            wsum += w;
            ssum += s;

#pragma unroll
            for (int k = 0; k < 8; k++) sacc[k] += s * xc[k];

            if (!more) break;
            idx = idn;
            pk = pkn;
            xcu = xcn;
        }
    }

#pragma unroll
    for (int k = 0; k < 8; k++)
        sacc[k] += __shfl_xor_sync(0xffffffffu, sacc[k], 16);
    wsum += __shfl_xor_sync(0xffffffffu, wsum, 16);
    ssum += __shfl_xor_sync(0xffffffffu, ssum, 16);

    float coef = (cnt > 0) ? __fdividef(1.0f, wsum * tanh_pos(sqrtf(g_normsq[r]))) : 0.f;

    int unit = 2 * l16 + hw;
    int sel = 4 * hw;
    const float4 xv = reinterpret_cast<const float4*>(x + (size_t)r * DIM)[unit];
    // x_star[k] = ssum*xr[k] - sacc[k];  out = x - coef*x_star
    reinterpret_cast<float4*>(out + (size_t)r * DIM)[unit] =
        make_float4(xv.x - coef * (ssum * xr[sel + 0] - sacc[sel + 0]),
                    xv.y - coef * (ssum * xr[sel + 1] - sacc[sel + 1]),
                    xv.z - coef * (ssum * xr[sel + 2] - sacc[sel + 2]),
                    xv.w - coef * (ssum * xr[sel + 3] - sacc[sel + 3]));
}

// ---------------- launch ----------------
// Order keeps gemm2 as the 6th launch (ncu -s 5 -c 1 captures it)
extern "C" void kernel_launch(void* const* d_in, const int* in_sizes, int n_in,
                              void* d_out, int out_size) {
    const float* x     = (const float*)d_in[0];
    const int*   ei    = (const int*)d_in[1];   // JAX emits int32
    const float* ew    = (const float*)d_in[2];
    const float* Wchi  = (const float*)d_in[3];
    const float* Wphi  = (const float*)d_in[4];
    const float* Wvphi = (const float*)d_in[5];

    int nNodes = in_sizes[0] / DIM;
    if (nNodes > N_NODES_MAX) nNodes = N_NODES_MAX;
    int E = in_sizes[2];
    if (E > E_MAX) E = E_MAX;

    void *pCnt, *pTot;
    cudaGetSymbolAddress(&pCnt, g_count);
    cudaGetSymbolAddress(&pTot, g_total);
    cudaMemsetAsync(pCnt, 0, (size_t)nNodes * sizeof(int), 0);
    cudaMemsetAsync(pTot, 0, sizeof(int), 0);

    prep1_kernel<<<DIM, DIM>>>(Wchi, Wphi);
    prep2_kernel<<<DIM, DIM>>>(Wvphi);

    int nUnits = nNodes * 64;
    conv_x_kernel<<<(nUnits + 255) / 256, 256>>>(x, nNodes);

    int smem = (2 * 128 * 68 + 128) * 4;
    cudaFuncSetAttribute(gemm2_kernel, cudaFuncAttributeMaxDynamicSharedMemorySize, smem);
    dim3 ggrid((nNodes + 127) / 128, 3);
    gemm2_kernel<<<ggrid, 256, smem>>>(nNodes);

    hist_kernel<<<(E + 255) / 256, 256>>>(ei, E);
    alloc_kernel<<<(nNodes + 255) / 256, 256>>>(nNodes);
    bucket_kernel<<<(E + 255) / 256, 256>>>(ei, ew, E);

    row_kernel<<<(nNodes * 32 + 255) / 256, 256>>>(x, (float*)d_out, nNodes);
}